// round 9
// baseline (speedup 1.0000x reference)
#include <cuda_runtime.h>
#include <cuda_fp16.h>
#include <cstddef>

#define NUM_USERS 200000
#define NUM_ITEMS 100000
#define N_NODES   (NUM_USERS + NUM_ITEMS)
#define DIM       64
#define NNZ       4000000

#define SCAN_TPB  1024
#define NB_SCAN   ((N_NODES + SCAN_TPB - 1) / SCAN_TPB)   // 293

// Scratch (allocation in kernel_launch is forbidden).
// fp16 embedding buffers: h0 = initial, h1..h3 = layer outputs.
__device__ __half g_h0[(size_t)N_NODES * DIM];
__device__ __half g_h1[(size_t)N_NODES * DIM];
__device__ __half g_h2[(size_t)N_NODES * DIM];
__device__ __half g_h3[(size_t)N_NODES * DIM];
__device__ int2   g_edges[NNZ];       // (col, val-bits), sorted by row
__device__ int    g_cnt[N_NODES];     // histogram of rows
__device__ int    g_base[N_NODES];    // within-block exclusive scan
__device__ int    g_row_ptr[N_NODES + 1];
__device__ int    g_cursor[N_NODES];  // running cursor for permute scatter
__device__ int    g_blk_sums[NB_SCAN];
__device__ int    g_blk_off[NB_SCAN];

// ---------------------------------------------------------------------------
// init: h0 = fp16(concat(user_emb, item_emb))
// Each thread converts 4 floats -> 4 halves (8 B store).
// ---------------------------------------------------------------------------
__global__ void init_half_kernel(const float* __restrict__ ue,
                                 const float* __restrict__ ie,
                                 __half* __restrict__ h0) {
    size_t i = (size_t)blockIdx.x * blockDim.x + threadIdx.x;   // float4 index
    const size_t total = (size_t)N_NODES * DIM / 4;
    if (i >= total) return;
    const size_t uf4 = (size_t)NUM_USERS * DIM / 4;
    float4 v;
    if (i < uf4) v = ((const float4*)ue)[i];
    else         v = ((const float4*)ie)[i - uf4];
    __half2 lo = __float22half2_rn(make_float2(v.x, v.y));
    __half2 hi = __float22half2_rn(make_float2(v.z, v.w));
    ((__half2*)h0)[i * 2]     = lo;
    ((__half2*)h0)[i * 2 + 1] = hi;
}

// ---------------------------------------------------------------------------
// CSR build: counting sort of edges by row
// ---------------------------------------------------------------------------
__global__ void zero_counters_kernel(int* __restrict__ cnt,
                                     int* __restrict__ cursor) {
    int i = blockIdx.x * blockDim.x + threadIdx.x;
    if (i < N_NODES) { cnt[i] = 0; cursor[i] = 0; }
}

__global__ void hist_kernel(const int* __restrict__ rows,
                            int* __restrict__ cnt) {
    int e = blockIdx.x * blockDim.x + threadIdx.x;
    if (e < NNZ) atomicAdd(&cnt[rows[e]], 1);
}

// Exclusive scan within each 1024-block; emit block totals.
__global__ void scan1_kernel(const int* __restrict__ cnt,
                             int* __restrict__ base,
                             int* __restrict__ blk_sums) {
    __shared__ int s[SCAN_TPB];
    int i = blockIdx.x * SCAN_TPB + threadIdx.x;
    int v = (i < N_NODES) ? cnt[i] : 0;
    s[threadIdx.x] = v;
    __syncthreads();
    for (int off = 1; off < SCAN_TPB; off <<= 1) {
        int t = (threadIdx.x >= off) ? s[threadIdx.x - off] : 0;
        __syncthreads();
        s[threadIdx.x] += t;
        __syncthreads();
    }
    if (i < N_NODES) base[i] = s[threadIdx.x] - v;   // exclusive
    if (threadIdx.x == SCAN_TPB - 1) blk_sums[blockIdx.x] = s[SCAN_TPB - 1];
}

// Exclusive scan over NB_SCAN (<=512) block sums in one block.
__global__ void scan2_kernel(const int* __restrict__ blk_sums,
                             int* __restrict__ blk_off) {
    __shared__ int s[512];
    int i = threadIdx.x;
    int v = (i < NB_SCAN) ? blk_sums[i] : 0;
    s[i] = v;
    __syncthreads();
    for (int off = 1; off < 512; off <<= 1) {
        int t = (i >= off) ? s[i - off] : 0;
        __syncthreads();
        s[i] += t;
        __syncthreads();
    }
    if (i < NB_SCAN) blk_off[i] = s[i] - v;          // exclusive
}

// row_ptr[i] = base[i] + blk_off[i>>10];  row_ptr[N_NODES] = NNZ
__global__ void rowptr_kernel(const int* __restrict__ base,
                              const int* __restrict__ blk_off,
                              int* __restrict__ row_ptr) {
    int i = blockIdx.x * blockDim.x + threadIdx.x;
    if (i < N_NODES) row_ptr[i] = base[i] + blk_off[i >> 10];
    if (i == 0)      row_ptr[N_NODES] = NNZ;
}

// Permute edges into row-sorted order as packed (col, val) int2.
__global__ void scatter_sort_kernel(const float* __restrict__ vals,
                                    const int*   __restrict__ rows,
                                    const int*   __restrict__ cols,
                                    const int*   __restrict__ row_ptr,
                                    int*         __restrict__ cursor,
                                    int2*        __restrict__ edges) {
    int e = blockIdx.x * blockDim.x + threadIdx.x;
    if (e >= NNZ) return;
    int r = rows[e];
    int p = row_ptr[r] + atomicAdd(&cursor[r], 1);
    edges[p] = make_int2(cols[e], __float_as_int(vals[e]));
}

// ---------------------------------------------------------------------------
// spmm_csr on fp16 embeddings: one warp per row, lane owns half2 slot `lane`.
//   acc(fp32) = sum over row's edges of v * x_h[c];  y_h[r] = fp16(acc)
// No atomics; pure gather + single coalesced 128 B row write.
// ---------------------------------------------------------------------------
__global__ void __launch_bounds__(256)
spmm_h_kernel(const int*    __restrict__ row_ptr,
              const int2*   __restrict__ edges,
              const __half* __restrict__ x,
              __half*       __restrict__ y) {
    int w    = (int)(((size_t)blockIdx.x * blockDim.x + threadIdx.x) >> 5);
    int lane = threadIdx.x & 31;
    if (w >= N_NODES) return;

    int s = __ldg(row_ptr + w);
    int e = __ldg(row_ptr + w + 1);

    float2 acc = make_float2(0.f, 0.f);
    int i = s;
    // 4-edge unroll for memory-level parallelism
    for (; i + 3 < e; i += 4) {
        int2 e0 = __ldg(edges + i);
        int2 e1 = __ldg(edges + i + 1);
        int2 e2 = __ldg(edges + i + 2);
        int2 e3 = __ldg(edges + i + 3);
        float2 x0 = __half22float2(__ldg((const __half2*)(x + (size_t)e0.x * DIM) + lane));
        float2 x1 = __half22float2(__ldg((const __half2*)(x + (size_t)e1.x * DIM) + lane));
        float2 x2 = __half22float2(__ldg((const __half2*)(x + (size_t)e2.x * DIM) + lane));
        float2 x3 = __half22float2(__ldg((const __half2*)(x + (size_t)e3.x * DIM) + lane));
        float v0 = __int_as_float(e0.y);
        float v1 = __int_as_float(e1.y);
        float v2 = __int_as_float(e2.y);
        float v3 = __int_as_float(e3.y);
        acc.x += v0 * x0.x + v1 * x1.x + v2 * x2.x + v3 * x3.x;
        acc.y += v0 * x0.y + v1 * x1.y + v2 * x2.y + v3 * x3.y;
    }
    for (; i < e; ++i) {
        int2 e0 = __ldg(edges + i);
        float2 x0 = __half22float2(__ldg((const __half2*)(x + (size_t)e0.x * DIM) + lane));
        float v0 = __int_as_float(e0.y);
        acc.x += v0 * x0.x;
        acc.y += v0 * x0.y;
    }

    ((__half2*)(y + (size_t)w * DIM))[lane] = __float22half2_rn(acc);
}

// ---------------------------------------------------------------------------
// final: out = 0.25 * (emb0_fp32 + h1 + h2 + h3)
// Thread handles 4 elements (float4 init read, float4 out write).
// ---------------------------------------------------------------------------
__global__ void final_kernel(const float*  __restrict__ ue,
                             const float*  __restrict__ ie,
                             const __half* __restrict__ h1,
                             const __half* __restrict__ h2,
                             const __half* __restrict__ h3,
                             float* __restrict__ out) {
    size_t i = (size_t)blockIdx.x * blockDim.x + threadIdx.x;   // float4 index
    const size_t total = (size_t)N_NODES * DIM / 4;
    if (i >= total) return;
    const size_t uf4 = (size_t)NUM_USERS * DIM / 4;
    float4 v;
    if (i < uf4) v = ((const float4*)ue)[i];
    else         v = ((const float4*)ie)[i - uf4];

    float2 a0 = __half22float2(((const __half2*)h1)[i * 2]);
    float2 a1 = __half22float2(((const __half2*)h1)[i * 2 + 1]);
    float2 b0 = __half22float2(((const __half2*)h2)[i * 2]);
    float2 b1 = __half22float2(((const __half2*)h2)[i * 2 + 1]);
    float2 c0 = __half22float2(((const __half2*)h3)[i * 2]);
    float2 c1 = __half22float2(((const __half2*)h3)[i * 2 + 1]);

    float4 o;
    o.x = 0.25f * (v.x + a0.x + b0.x + c0.x);
    o.y = 0.25f * (v.y + a0.y + b0.y + c0.y);
    o.z = 0.25f * (v.z + a1.x + b1.x + c1.x);
    o.w = 0.25f * (v.w + a1.y + b1.y + c1.y);
    ((float4*)out)[i] = o;
}

// ---------------------------------------------------------------------------
// launch
// ---------------------------------------------------------------------------
extern "C" void kernel_launch(void* const* d_in, const int* in_sizes, int n_in,
                              void* d_out, int out_size) {
    const float* ue   = (const float*)d_in[0];
    const float* ie   = (const float*)d_in[1];
    const float* vals = (const float*)d_in[2];
    const int*   rows = (const int*)d_in[3];
    const int*   cols = (const int*)d_in[4];
    float* out = (float*)d_out;

    __half *h0, *h1, *h2, *h3;
    int2* edges;
    int *cnt, *base, *row_ptr, *cursor, *blk_sums, *blk_off;
    cudaGetSymbolAddress((void**)&h0, g_h0);
    cudaGetSymbolAddress((void**)&h1, g_h1);
    cudaGetSymbolAddress((void**)&h2, g_h2);
    cudaGetSymbolAddress((void**)&h3, g_h3);
    cudaGetSymbolAddress((void**)&edges, g_edges);
    cudaGetSymbolAddress((void**)&cnt, g_cnt);
    cudaGetSymbolAddress((void**)&base, g_base);
    cudaGetSymbolAddress((void**)&row_ptr, g_row_ptr);
    cudaGetSymbolAddress((void**)&cursor, g_cursor);
    cudaGetSymbolAddress((void**)&blk_sums, g_blk_sums);
    cudaGetSymbolAddress((void**)&blk_off, g_blk_off);

    const int TPB = 256;
    const size_t nf4 = (size_t)N_NODES * DIM / 4;           // 4.8M float4s
    const int grid_f4   = (int)((nf4 + TPB - 1) / TPB);
    const int grid_node = (N_NODES + TPB - 1) / TPB;
    const int grid_edge = (NNZ + TPB - 1) / TPB;
    const size_t spmm_threads = (size_t)N_NODES * 32;       // warp per row
    const int grid_spmm = (int)((spmm_threads + TPB - 1) / TPB);

    // ---- build row-sorted CSR (amortized over 3 layers) ----
    zero_counters_kernel<<<grid_node, TPB>>>(cnt, cursor);
    hist_kernel<<<grid_edge, TPB>>>(rows, cnt);
    scan1_kernel<<<NB_SCAN, SCAN_TPB>>>(cnt, base, blk_sums);
    scan2_kernel<<<1, 512>>>(blk_sums, blk_off);
    rowptr_kernel<<<grid_node, TPB>>>(base, blk_off, row_ptr);
    scatter_sort_kernel<<<grid_edge, TPB>>>(vals, rows, cols, row_ptr,
                                            cursor, edges);

    // ---- h0 = fp16(concat embeddings) ----
    init_half_kernel<<<grid_f4, TPB>>>(ue, ie, h0);

    // ---- 3 layers of fp16 SpMM ----
    spmm_h_kernel<<<grid_spmm, TPB>>>(row_ptr, edges, h0, h1);
    spmm_h_kernel<<<grid_spmm, TPB>>>(row_ptr, edges, h1, h2);
    spmm_h_kernel<<<grid_spmm, TPB>>>(row_ptr, edges, h2, h3);

    // ---- out = 0.25 * (emb0 + h1 + h2 + h3) ----
    final_kernel<<<grid_f4, TPB>>>(ue, ie, h1, h2, h3, out);
}

// round 10
// speedup vs baseline: 1.0557x; 1.0557x over previous
#include <cuda_runtime.h>
#include <cuda_fp16.h>
#include <cstddef>

#define NUM_USERS 200000
#define NUM_ITEMS 100000
#define N_NODES   (NUM_USERS + NUM_ITEMS)
#define DIM       64
#define NNZ       4000000

#define SCAN_TPB  1024
#define NB_SCAN   ((N_NODES + SCAN_TPB - 1) / SCAN_TPB)   // 293

// Scratch (allocation in kernel_launch is forbidden).
__device__ __half g_h0[(size_t)N_NODES * DIM];
__device__ __half g_h1[(size_t)N_NODES * DIM];
__device__ __half g_h2[(size_t)N_NODES * DIM];
__device__ __half g_h3[(size_t)N_NODES * DIM];
__device__ __align__(16) int2 g_edges[NNZ];   // (col, val-bits), row-sorted
__device__ int    g_cnt[N_NODES];
__device__ int    g_base[N_NODES];
__device__ int    g_row_ptr[N_NODES + 1];
__device__ int    g_cursor[N_NODES];
__device__ int    g_blk_sums[NB_SCAN];
__device__ int    g_blk_off[NB_SCAN];

// ---------------------------------------------------------------------------
// init: h0 = fp16(concat(user_emb, item_emb))
// ---------------------------------------------------------------------------
__global__ void init_half_kernel(const float* __restrict__ ue,
                                 const float* __restrict__ ie,
                                 __half* __restrict__ h0) {
    size_t i = (size_t)blockIdx.x * blockDim.x + threadIdx.x;   // float4 index
    const size_t total = (size_t)N_NODES * DIM / 4;
    if (i >= total) return;
    const size_t uf4 = (size_t)NUM_USERS * DIM / 4;
    float4 v;
    if (i < uf4) v = ((const float4*)ue)[i];
    else         v = ((const float4*)ie)[i - uf4];
    __half2 lo = __float22half2_rn(make_float2(v.x, v.y));
    __half2 hi = __float22half2_rn(make_float2(v.z, v.w));
    ((__half2*)h0)[i * 2]     = lo;
    ((__half2*)h0)[i * 2 + 1] = hi;
}

// ---------------------------------------------------------------------------
// CSR build: counting sort of edges by row
// ---------------------------------------------------------------------------
__global__ void zero_counters_kernel(int* __restrict__ cnt,
                                     int* __restrict__ cursor) {
    int i = blockIdx.x * blockDim.x + threadIdx.x;
    if (i < N_NODES) { cnt[i] = 0; cursor[i] = 0; }
}

__global__ void hist_kernel(const int* __restrict__ rows,
                            int* __restrict__ cnt) {
    int e = blockIdx.x * blockDim.x + threadIdx.x;
    if (e < NNZ) atomicAdd(&cnt[rows[e]], 1);
}

__global__ void scan1_kernel(const int* __restrict__ cnt,
                             int* __restrict__ base,
                             int* __restrict__ blk_sums) {
    __shared__ int s[SCAN_TPB];
    int i = blockIdx.x * SCAN_TPB + threadIdx.x;
    int v = (i < N_NODES) ? cnt[i] : 0;
    s[threadIdx.x] = v;
    __syncthreads();
    for (int off = 1; off < SCAN_TPB; off <<= 1) {
        int t = (threadIdx.x >= off) ? s[threadIdx.x - off] : 0;
        __syncthreads();
        s[threadIdx.x] += t;
        __syncthreads();
    }
    if (i < N_NODES) base[i] = s[threadIdx.x] - v;   // exclusive
    if (threadIdx.x == SCAN_TPB - 1) blk_sums[blockIdx.x] = s[SCAN_TPB - 1];
}

__global__ void scan2_kernel(const int* __restrict__ blk_sums,
                             int* __restrict__ blk_off) {
    __shared__ int s[512];
    int i = threadIdx.x;
    int v = (i < NB_SCAN) ? blk_sums[i] : 0;
    s[i] = v;
    __syncthreads();
    for (int off = 1; off < 512; off <<= 1) {
        int t = (i >= off) ? s[i - off] : 0;
        __syncthreads();
        s[i] += t;
        __syncthreads();
    }
    if (i < NB_SCAN) blk_off[i] = s[i] - v;          // exclusive
}

__global__ void rowptr_kernel(const int* __restrict__ base,
                              const int* __restrict__ blk_off,
                              int* __restrict__ row_ptr) {
    int i = blockIdx.x * blockDim.x + threadIdx.x;
    if (i < N_NODES) row_ptr[i] = base[i] + blk_off[i >> 10];
    if (i == 0)      row_ptr[N_NODES] = NNZ;
}

__global__ void scatter_sort_kernel(const float* __restrict__ vals,
                                    const int*   __restrict__ rows,
                                    const int*   __restrict__ cols,
                                    const int*   __restrict__ row_ptr,
                                    int*         __restrict__ cursor,
                                    int2*        __restrict__ edges) {
    int e = blockIdx.x * blockDim.x + threadIdx.x;
    if (e >= NNZ) return;
    int r = rows[e];
    int p = row_ptr[r] + atomicAdd(&cursor[r], 1);
    edges[p] = make_int2(cols[e], __float_as_int(vals[e]));
}

// ---------------------------------------------------------------------------
// spmm: one warp per row; 16 lanes per edge -> TWO edges per warp LDG.
// Lane layout: half = lane>>4 selects edge of the pair, sub = lane&15 selects
// the 8-byte chunk (4 halves) of the 128-byte fp16 row.
// Accumulate fp32 in float4/lane; shfl_xor(16) merges the two edge-halves.
// ---------------------------------------------------------------------------
__device__ __forceinline__ void fetch_acc(const __half* __restrict__ x,
                                          int c, float v, int sub, float4& acc) {
    uint2 d = __ldg((const uint2*)(x + (size_t)c * DIM) + sub);
    float2 lo = __half22float2(*(const __half2*)&d.x);
    float2 hi = __half22float2(*(const __half2*)&d.y);
    acc.x += v * lo.x;
    acc.y += v * lo.y;
    acc.z += v * hi.x;
    acc.w += v * hi.y;
}

__global__ void __launch_bounds__(256)
spmm_h_kernel(const int*    __restrict__ row_ptr,
              const int2*   __restrict__ edges,
              const __half* __restrict__ x,
              __half*       __restrict__ y) {
    int w    = (int)(((size_t)blockIdx.x * blockDim.x + threadIdx.x) >> 5);
    int lane = threadIdx.x & 31;
    if (w >= N_NODES) return;

    int s = __ldg(row_ptr + w);
    int e = __ldg(row_ptr + w + 1);

    int half = lane >> 4;
    int sub  = lane & 15;
    float4 acc = make_float4(0.f, 0.f, 0.f, 0.f);

    int i = s;
    // head peel to reach even (16B-aligned) edge index
    if ((i & 1) && i < e) {
        int2 E = __ldg(edges + i);
        float v = half ? 0.f : __int_as_float(E.y);
        fetch_acc(x, E.x, v, sub, acc);
        ++i;
    }
    // 4 edges per iteration: 2 int4 edge loads + 2 paired x gathers
    for (; i + 3 < e; i += 4) {
        int4 E0 = __ldg((const int4*)(edges + i));
        int4 E1 = __ldg((const int4*)(edges + i + 2));
        {
            int   c = half ? E0.z : E0.x;
            float v = __int_as_float(half ? E0.w : E0.y);
            fetch_acc(x, c, v, sub, acc);
        }
        {
            int   c = half ? E1.z : E1.x;
            float v = __int_as_float(half ? E1.w : E1.y);
            fetch_acc(x, c, v, sub, acc);
        }
    }
    // 2-edge step
    for (; i + 1 < e; i += 2) {
        int4 E0 = __ldg((const int4*)(edges + i));
        int   c = half ? E0.z : E0.x;
        float v = __int_as_float(half ? E0.w : E0.y);
        fetch_acc(x, c, v, sub, acc);
    }
    // tail single edge
    if (i < e) {
        int2 E = __ldg(edges + i);
        float v = half ? 0.f : __int_as_float(E.y);
        fetch_acc(x, E.x, v, sub, acc);
    }

    // merge the two edge-halves (lane l += lane l+16)
    acc.x += __shfl_xor_sync(0xffffffffu, acc.x, 16);
    acc.y += __shfl_xor_sync(0xffffffffu, acc.y, 16);
    acc.z += __shfl_xor_sync(0xffffffffu, acc.z, 16);
    acc.w += __shfl_xor_sync(0xffffffffu, acc.w, 16);

    if (half == 0) {
        __half2 lo = __float22half2_rn(make_float2(acc.x, acc.y));
        __half2 hi = __float22half2_rn(make_float2(acc.z, acc.w));
        uint2 d;
        d.x = *(const unsigned int*)&lo;
        d.y = *(const unsigned int*)&hi;
        ((uint2*)(y + (size_t)w * DIM))[sub] = d;
    }
}

// ---------------------------------------------------------------------------
// final: out = 0.25 * (emb0_fp32 + h1 + h2 + h3)
// ---------------------------------------------------------------------------
__global__ void final_kernel(const float*  __restrict__ ue,
                             const float*  __restrict__ ie,
                             const __half* __restrict__ h1,
                             const __half* __restrict__ h2,
                             const __half* __restrict__ h3,
                             float* __restrict__ out) {
    size_t i = (size_t)blockIdx.x * blockDim.x + threadIdx.x;   // float4 index
    const size_t total = (size_t)N_NODES * DIM / 4;
    if (i >= total) return;
    const size_t uf4 = (size_t)NUM_USERS * DIM / 4;
    float4 v;
    if (i < uf4) v = ((const float4*)ue)[i];
    else         v = ((const float4*)ie)[i - uf4];

    float2 a0 = __half22float2(((const __half2*)h1)[i * 2]);
    float2 a1 = __half22float2(((const __half2*)h1)[i * 2 + 1]);
    float2 b0 = __half22float2(((const __half2*)h2)[i * 2]);
    float2 b1 = __half22float2(((const __half2*)h2)[i * 2 + 1]);
    float2 c0 = __half22float2(((const __half2*)h3)[i * 2]);
    float2 c1 = __half22float2(((const __half2*)h3)[i * 2 + 1]);

    float4 o;
    o.x = 0.25f * (v.x + a0.x + b0.x + c0.x);
    o.y = 0.25f * (v.y + a0.y + b0.y + c0.y);
    o.z = 0.25f * (v.z + a1.x + b1.x + c1.x);
    o.w = 0.25f * (v.w + a1.y + b1.y + c1.y);
    ((float4*)out)[i] = o;
}

// ---------------------------------------------------------------------------
// launch
// ---------------------------------------------------------------------------
extern "C" void kernel_launch(void* const* d_in, const int* in_sizes, int n_in,
                              void* d_out, int out_size) {
    const float* ue   = (const float*)d_in[0];
    const float* ie   = (const float*)d_in[1];
    const float* vals = (const float*)d_in[2];
    const int*   rows = (const int*)d_in[3];
    const int*   cols = (const int*)d_in[4];
    float* out = (float*)d_out;

    __half *h0, *h1, *h2, *h3;
    int2* edges;
    int *cnt, *base, *row_ptr, *cursor, *blk_sums, *blk_off;
    cudaGetSymbolAddress((void**)&h0, g_h0);
    cudaGetSymbolAddress((void**)&h1, g_h1);
    cudaGetSymbolAddress((void**)&h2, g_h2);
    cudaGetSymbolAddress((void**)&h3, g_h3);
    cudaGetSymbolAddress((void**)&edges, g_edges);
    cudaGetSymbolAddress((void**)&cnt, g_cnt);
    cudaGetSymbolAddress((void**)&base, g_base);
    cudaGetSymbolAddress((void**)&row_ptr, g_row_ptr);
    cudaGetSymbolAddress((void**)&cursor, g_cursor);
    cudaGetSymbolAddress((void**)&blk_sums, g_blk_sums);
    cudaGetSymbolAddress((void**)&blk_off, g_blk_off);

    const int TPB = 256;
    const size_t nf4 = (size_t)N_NODES * DIM / 4;           // 4.8M float4s
    const int grid_f4   = (int)((nf4 + TPB - 1) / TPB);
    const int grid_node = (N_NODES + TPB - 1) / TPB;
    const int grid_edge = (NNZ + TPB - 1) / TPB;
    const size_t spmm_threads = (size_t)N_NODES * 32;       // warp per row
    const int grid_spmm = (int)((spmm_threads + TPB - 1) / TPB);

    // ---- build row-sorted CSR (amortized over 3 layers) ----
    zero_counters_kernel<<<grid_node, TPB>>>(cnt, cursor);
    hist_kernel<<<grid_edge, TPB>>>(rows, cnt);
    scan1_kernel<<<NB_SCAN, SCAN_TPB>>>(cnt, base, blk_sums);
    scan2_kernel<<<1, 512>>>(blk_sums, blk_off);
    rowptr_kernel<<<grid_node, TPB>>>(base, blk_off, row_ptr);
    scatter_sort_kernel<<<grid_edge, TPB>>>(vals, rows, cols, row_ptr,
                                            cursor, edges);

    // ---- h0 = fp16(concat embeddings) ----
    init_half_kernel<<<grid_f4, TPB>>>(ue, ie, h0);

    // ---- 3 layers of fp16 SpMM ----
    spmm_h_kernel<<<grid_spmm, TPB>>>(row_ptr, edges, h0, h1);
    spmm_h_kernel<<<grid_spmm, TPB>>>(row_ptr, edges, h1, h2);
    spmm_h_kernel<<<grid_spmm, TPB>>>(row_ptr, edges, h2, h3);

    // ---- out = 0.25 * (emb0 + h1 + h2 + h3) ----
    final_kernel<<<grid_f4, TPB>>>(ue, ie, h1, h2, h3, out);
}